// round 5
// baseline (speedup 1.0000x reference)
#include <cuda_runtime.h>
#include <math.h>
#include <stdint.h>

// Closed-form collapse of the 4-qubit circuit:
//   m0 = cos(p4)cos(p0)cos(t0) - sin(p4)sin(t1+p1)sin(t0)
//   m1 = cos(t1+p1)cos(p0)cos(t0)
//   m2 = cos(t2)
//   m3 = cos(p3)cos(t2)cos(t3)
// logits[b,k] = sum_patch m.W[k] + bias[k]; out = log_softmax(logits).
//
// grid=128, cluster=2: each image is split across 2 clustered CTAs
// (625 patch-pairs each, one pair per thread). Rank 1 ships its float2
// partial to rank 0's SMEM via DSMEM; rank 0 combines after cluster.sync
// and writes the 2-class log_softmax directly.

#define BLK    640
#define ACTIVE 625     // pairs per half-image

__device__ __forceinline__ uint32_t smem_u32(const void* p) {
    uint32_t a;
    asm("{ .reg .u64 t; cvta.to.shared.u64 t, %1; cvt.u32.u64 %0, t; }"
        : "=r"(a) : "l"(p));
    return a;
}

__global__ __launch_bounds__(BLK) __cluster_dims__(2, 1, 1)
void fused_kernel(
    const float* __restrict__ x,
    const float* __restrict__ W,
    const float* __restrict__ bias,
    const float* __restrict__ qp,
    float* __restrict__ out)
{
    __shared__ float2 warpred[BLK / 32];   // 20
    __shared__ float2 slots[2];            // [rank0 partial, rank1 partial]

    const int tid  = threadIdx.x;
    const int img  = blockIdx.x >> 1;
    uint32_t rank;
    asm("mov.u32 %0, %%cluster_ctarank;" : "=r"(rank));

    // Circuit constants (broadcast loads; MUFU overlaps x-load latency)
    float sp4, cp4;
    __sincosf(qp[4], &sp4, &cp4);
    const float cp0 = __cosf(qp[0]);
    const float cp3 = __cosf(qp[3]);
    const float P1  = qp[1];
    const float K1  = cp4 * cp0;

    float acc0 = 0.f, acc1 = 0.f;

    if (tid < ACTIVE) {
        const int q  = (int)rank * ACTIVE + tid;  // pair 0..1249
        const int i  = q / 25;                    // patch row 0..49
        const int jp = q - i * 25;                // pair col 0..24
        const int p  = i * 50 + 2 * jp;           // patch index

        const float* xb = x + img * 10000;
        const float4 r0 = *reinterpret_cast<const float4*>(xb + 200 * i + 4 * jp);
        const float4 r1 = *reinterpret_cast<const float4*>(xb + 200 * i + 100 + 4 * jp);
        const float4 w00 = *reinterpret_cast<const float4*>(W + p * 4);
        const float4 w01 = *reinterpret_cast<const float4*>(W + p * 4 + 4);
        const float4 w10 = *reinterpret_cast<const float4*>(W + 10000 + p * 4);
        const float4 w11 = *reinterpret_cast<const float4*>(W + 10000 + p * 4 + 4);

        // patch A: t = (r0.x, r0.y, r1.x, r1.y)
        {
            float s0, c0, sa, ca;
            __sincosf(r0.x, &s0, &c0);
            __sincosf(r0.y + P1, &sa, &ca);
            const float ct2 = __cosf(r1.x);
            const float ct3 = __cosf(r1.y);
            const float m0 = fmaf(K1, c0, -sp4 * sa * s0);
            const float m1 = cp0 * ca * c0;
            const float m3 = cp3 * ct2 * ct3;
            acc0 = fmaf(m0, w00.x, fmaf(m1, w00.y, fmaf(ct2, w00.z, fmaf(m3, w00.w, acc0))));
            acc1 = fmaf(m0, w10.x, fmaf(m1, w10.y, fmaf(ct2, w10.z, fmaf(m3, w10.w, acc1))));
        }
        // patch B: t = (r0.z, r0.w, r1.z, r1.w)
        {
            float s0, c0, sa, ca;
            __sincosf(r0.z, &s0, &c0);
            __sincosf(r0.w + P1, &sa, &ca);
            const float ct2 = __cosf(r1.z);
            const float ct3 = __cosf(r1.w);
            const float m0 = fmaf(K1, c0, -sp4 * sa * s0);
            const float m1 = cp0 * ca * c0;
            const float m3 = cp3 * ct2 * ct3;
            acc0 = fmaf(m0, w01.x, fmaf(m1, w01.y, fmaf(ct2, w01.z, fmaf(m3, w01.w, acc0))));
            acc1 = fmaf(m0, w11.x, fmaf(m1, w11.y, fmaf(ct2, w11.z, fmaf(m3, w11.w, acc1))));
        }
    }

    // deterministic reduction: warp shuffle -> smem -> warp 0 shuffle
#pragma unroll
    for (int off = 16; off > 0; off >>= 1) {
        acc0 += __shfl_down_sync(0xFFFFFFFFu, acc0, off);
        acc1 += __shfl_down_sync(0xFFFFFFFFu, acc1, off);
    }
    if ((tid & 31) == 0) warpred[tid >> 5] = make_float2(acc0, acc1);
    __syncthreads();

    if (tid < 32) {
        float2 v = (tid < BLK / 32) ? warpred[tid] : make_float2(0.f, 0.f);
#pragma unroll
        for (int off = 16; off > 0; off >>= 1) {
            v.x += __shfl_down_sync(0xFFFFFFFFu, v.x, off);
            v.y += __shfl_down_sync(0xFFFFFFFFu, v.y, off);
        }
        if (tid == 0) {
            if (rank == 0) {
                slots[0] = v;   // own partial, local smem
            } else {
                // ship partial to rank 0's slots[1] via DSMEM
                const uint64_t pack = (uint64_t)__float_as_uint(v.x)
                                    | ((uint64_t)__float_as_uint(v.y) << 32);
                uint32_t laddr = smem_u32(&slots[1]);
                uint32_t raddr;
                asm("mapa.shared::cluster.u32 %0, %1, %2;"
                    : "=r"(raddr) : "r"(laddr), "r"(0));
                asm volatile("st.shared::cluster.b64 [%0], %1;"
                             :: "r"(raddr), "l"(pack) : "memory");
            }
        }
    }

    // cluster barrier: arrive has release semantics, wait has acquire
    asm volatile("barrier.cluster.arrive.aligned;" ::: "memory");
    asm volatile("barrier.cluster.wait.aligned;" ::: "memory");

    if (rank == 0 && tid == 0) {
        const float l0 = bias[0] + slots[0].x + slots[1].x;
        const float l1 = bias[1] + slots[0].y + slots[1].y;
        const float m   = fmaxf(l0, l1);
        const float lse = m + __logf(__expf(l0 - m) + __expf(l1 - m));
        out[img * 2 + 0] = l0 - lse;
        out[img * 2 + 1] = l1 - lse;
    }
}

extern "C" void kernel_launch(void* const* d_in, const int* in_sizes, int n_in,
                              void* d_out, int out_size)
{
    (void)in_sizes; (void)n_in; (void)out_size;
    const float* x    = (const float*)d_in[0];  // [64,100,100]
    const float* W    = (const float*)d_in[1];  // [2,10000]
    const float* bias = (const float*)d_in[2];  // [2]
    const float* qp   = (const float*)d_in[3];  // [6]

    fused_kernel<<<128, BLK>>>(x, W, bias, qp, (float*)d_out);
}

// round 6
// speedup vs baseline: 1.0047x; 1.0047x over previous
#include <cuda_runtime.h>
#include <math.h>

// Closed-form collapse of the 4-qubit circuit:
//   m0 = cos(p4)cos(p0)cos(t0) - sin(p4)sin(t1+p1)sin(t0)
//   m1 = cos(t1+p1)cos(p0)cos(t0)
//   m2 = cos(t2)
//   m3 = cos(p3)cos(t2)cos(t3)
// 2-class log_softmax depends only on d = l1 - l0:
//   out0 = -log(1+e^d), out1 = -log(1+e^-d)
// so accumulate a single dot against dW = W[1]-W[0].
//
// grid=64 (one block per image), 640 threads; threads 0..624 handle exactly
// two patch-pairs (4 patches). All loads issued up front for MLP.

#define BLK    640
#define ACTIVE 625     // 1250 pairs / 2

__device__ __forceinline__ void patch_dot(
    float t0, float t1, float t2, float t3,
    float K1, float sp4, float cp0, float cp3, float P1,
    const float4& dw, float& acc)
{
    float s0, c0, sa, ca;
    __sincosf(t0, &s0, &c0);
    __sincosf(t1 + P1, &sa, &ca);
    const float ct2 = __cosf(t2);
    const float ct3 = __cosf(t3);
    const float m0 = fmaf(K1, c0, -sp4 * sa * s0);
    const float m1 = cp0 * ca * c0;
    const float m3 = cp3 * ct2 * ct3;
    acc = fmaf(m0, dw.x, fmaf(m1, dw.y, fmaf(ct2, dw.z, fmaf(m3, dw.w, acc))));
}

__device__ __forceinline__ float4 f4sub(const float4 a, const float4 b) {
    return make_float4(a.x - b.x, a.y - b.y, a.z - b.z, a.w - b.w);
}

__global__ __launch_bounds__(BLK) void fused_kernel(
    const float* __restrict__ x,
    const float* __restrict__ W,
    const float* __restrict__ bias,
    const float* __restrict__ qp,
    float* __restrict__ out)
{
    const int tid = threadIdx.x;
    const int b   = blockIdx.x;

    // Circuit constants (broadcast loads; MUFU overlaps x-load latency)
    float sp4, cp4;
    __sincosf(qp[4], &sp4, &cp4);
    const float cp0 = __cosf(qp[0]);
    const float cp3 = __cosf(qp[3]);
    const float P1  = qp[1];
    const float K1  = cp4 * cp0;

    float acc = 0.f;

    if (tid < ACTIVE) {
        const float* xb = x + b * 10000;

        const int qA  = tid;
        const int qB  = tid + ACTIVE;
        const int iA  = qA / 25, jpA = qA - iA * 25;
        const int iB  = qB / 25, jpB = qB - iB * 25;
        const int pA  = iA * 50 + 2 * jpA;
        const int pB  = iB * 50 + 2 * jpB;

        // ---- issue ALL loads up front (12 independent 16B loads) ----
        const float4 rA0 = *reinterpret_cast<const float4*>(xb + 200 * iA + 4 * jpA);
        const float4 rA1 = *reinterpret_cast<const float4*>(xb + 200 * iA + 100 + 4 * jpA);
        const float4 rB0 = *reinterpret_cast<const float4*>(xb + 200 * iB + 4 * jpB);
        const float4 rB1 = *reinterpret_cast<const float4*>(xb + 200 * iB + 100 + 4 * jpB);
        const float4 wA00 = *reinterpret_cast<const float4*>(W + pA * 4);
        const float4 wA01 = *reinterpret_cast<const float4*>(W + pA * 4 + 4);
        const float4 wA10 = *reinterpret_cast<const float4*>(W + 10000 + pA * 4);
        const float4 wA11 = *reinterpret_cast<const float4*>(W + 10000 + pA * 4 + 4);
        const float4 wB00 = *reinterpret_cast<const float4*>(W + pB * 4);
        const float4 wB01 = *reinterpret_cast<const float4*>(W + pB * 4 + 4);
        const float4 wB10 = *reinterpret_cast<const float4*>(W + 10000 + pB * 4);
        const float4 wB11 = *reinterpret_cast<const float4*>(W + 10000 + pB * 4 + 4);

        const float4 dA0 = f4sub(wA10, wA00);
        const float4 dA1 = f4sub(wA11, wA01);
        const float4 dB0 = f4sub(wB10, wB00);
        const float4 dB1 = f4sub(wB11, wB01);

        patch_dot(rA0.x, rA0.y, rA1.x, rA1.y, K1, sp4, cp0, cp3, P1, dA0, acc);
        patch_dot(rA0.z, rA0.w, rA1.z, rA1.w, K1, sp4, cp0, cp3, P1, dA1, acc);
        patch_dot(rB0.x, rB0.y, rB1.x, rB1.y, K1, sp4, cp0, cp3, P1, dB0, acc);
        patch_dot(rB0.z, rB0.w, rB1.z, rB1.w, K1, sp4, cp0, cp3, P1, dB1, acc);
    }

    // deterministic reduction: warp shuffle -> smem -> warp 0 shuffle
#pragma unroll
    for (int off = 16; off > 0; off >>= 1)
        acc += __shfl_down_sync(0xFFFFFFFFu, acc, off);

    __shared__ float warpred[BLK / 32];   // 20 entries
    if ((tid & 31) == 0) warpred[tid >> 5] = acc;
    __syncthreads();

    if (tid < 32) {
        float v = (tid < BLK / 32) ? warpred[tid] : 0.f;
#pragma unroll
        for (int off = 16; off > 0; off >>= 1)
            v += __shfl_down_sync(0xFFFFFFFFu, v, off);
        if (tid == 0) {
            const float d  = v + (bias[1] - bias[0]);   // l1 - l0
            // out0 = -log(1+e^d), out1 = -log(1+e^-d); numerically stable form
            const float ad = fabsf(d);
            const float t  = __logf(1.f + __expf(-ad));  // log1p(e^-|d|)
            const float lo = -(ad + t);                  // for the smaller logit
            const float hi = -t;                         // for the larger logit
            out[b * 2 + 0] = (d >= 0.f) ? lo : hi;
            out[b * 2 + 1] = (d >= 0.f) ? hi : lo;
        }
    }
}

extern "C" void kernel_launch(void* const* d_in, const int* in_sizes, int n_in,
                              void* d_out, int out_size)
{
    (void)in_sizes; (void)n_in; (void)out_size;
    const float* x    = (const float*)d_in[0];  // [64,100,100]
    const float* W    = (const float*)d_in[1];  // [2,10000]
    const float* bias = (const float*)d_in[2];  // [2]
    const float* qp   = (const float*)d_in[3];  // [6]

    fused_kernel<<<64, BLK>>>(x, W, bias, qp, (float*)d_out);
}

// round 7
// speedup vs baseline: 1.0385x; 1.0337x over previous
#include <cuda_runtime.h>
#include <math.h>

// Closed-form collapse of the 4-qubit circuit:
//   m0 = cos(p4)cos(p0)cos(t0) - sin(p4)sin(t1+p1)sin(t0)
//   m1 = cos(t1+p1)cos(p0)cos(t0)
//   m2 = cos(t2)
//   m3 = cos(p3)cos(t2)cos(t3)
// 2-class log_softmax depends only on d = l1 - l0:
//   out0 = -log(1+e^d), out1 = -log(1+e^-d)
// so accumulate a single dot against dW = W[1]-W[0].
//
// grid=64 (one block per image), 640 threads; threads 0..624 handle exactly
// two patch-pairs. Pair B = pair A + 625 = same column, row+25, so all of
// pair B's addresses are pair A's + 5000 floats (no second division).

#define BLK    640
#define ACTIVE 625     // 1250 pairs / 2; 625 = 25*25

__device__ __forceinline__ void patch_dot(
    float t0, float t1, float t2, float t3,
    float K1, float sp4, float cp0, float cp3, float P1,
    const float4& dw, float& acc)
{
    float s0, c0, sa, ca;
    __sincosf(t0, &s0, &c0);
    __sincosf(t1 + P1, &sa, &ca);
    const float ct2 = __cosf(t2);
    const float ct3 = __cosf(t3);
    const float m0 = fmaf(K1, c0, -sp4 * sa * s0);
    const float m1 = cp0 * ca * c0;
    const float m3 = cp3 * ct2 * ct3;
    acc = fmaf(m0, dw.x, fmaf(m1, dw.y, fmaf(ct2, dw.z, fmaf(m3, dw.w, acc))));
}

__device__ __forceinline__ float4 f4sub(const float4 a, const float4 b) {
    return make_float4(a.x - b.x, a.y - b.y, a.z - b.z, a.w - b.w);
}

__global__ __launch_bounds__(BLK) void fused_kernel(
    const float* __restrict__ x,
    const float* __restrict__ W,
    const float* __restrict__ bias,
    const float* __restrict__ qp,
    float* __restrict__ out)
{
    const int tid = threadIdx.x;
    const int b   = blockIdx.x;

    // Circuit constants (broadcast loads; MUFU overlaps x-load latency)
    float sp4, cp4;
    __sincosf(qp[4], &sp4, &cp4);
    const float cp0 = __cosf(qp[0]);
    const float cp3 = __cosf(qp[3]);
    const float P1  = qp[1];
    const float K1  = cp4 * cp0;

    float acc = 0.f;

    if (tid < ACTIVE) {
        const int i  = tid / 25;              // patch row 0..24 (pair A)
        const int jp = tid - i * 25;          // pair column 0..24
        const int p  = i * 50 + 2 * jp;       // patch index (pair A)

        // Pair B is pair A shifted by 25 patch-rows:
        //   x offset +5000 floats, W offset +5000*4? No: pB = p + 1250,
        //   W element offset = pB*4 = p*4 + 5000.
        const float* xA = x + b * 10000 + 200 * i + 4 * jp;
        const float* wA = W + p * 4;

        // ---- issue ALL loads up front (12 independent 16B loads,
        //      B-addresses are A-addresses + fixed immediates) ----
        const float4 rA0 = *reinterpret_cast<const float4*>(xA);
        const float4 rA1 = *reinterpret_cast<const float4*>(xA + 100);
        const float4 rB0 = *reinterpret_cast<const float4*>(xA + 5000);
        const float4 rB1 = *reinterpret_cast<const float4*>(xA + 5100);
        const float4 wA00 = *reinterpret_cast<const float4*>(wA);
        const float4 wA01 = *reinterpret_cast<const float4*>(wA + 4);
        const float4 wB00 = *reinterpret_cast<const float4*>(wA + 5000);
        const float4 wB01 = *reinterpret_cast<const float4*>(wA + 5004);
        const float4 wA10 = *reinterpret_cast<const float4*>(wA + 10000);
        const float4 wA11 = *reinterpret_cast<const float4*>(wA + 10004);
        const float4 wB10 = *reinterpret_cast<const float4*>(wA + 15000);
        const float4 wB11 = *reinterpret_cast<const float4*>(wA + 15004);

        const float4 dA0 = f4sub(wA10, wA00);
        const float4 dA1 = f4sub(wA11, wA01);
        const float4 dB0 = f4sub(wB10, wB00);
        const float4 dB1 = f4sub(wB11, wB01);

        patch_dot(rA0.x, rA0.y, rA1.x, rA1.y, K1, sp4, cp0, cp3, P1, dA0, acc);
        patch_dot(rA0.z, rA0.w, rA1.z, rA1.w, K1, sp4, cp0, cp3, P1, dA1, acc);
        patch_dot(rB0.x, rB0.y, rB1.x, rB1.y, K1, sp4, cp0, cp3, P1, dB0, acc);
        patch_dot(rB0.z, rB0.w, rB1.z, rB1.w, K1, sp4, cp0, cp3, P1, dB1, acc);
    }

    // deterministic reduction: warp shuffle -> smem -> warp 0 shuffle
#pragma unroll
    for (int off = 16; off > 0; off >>= 1)
        acc += __shfl_down_sync(0xFFFFFFFFu, acc, off);

    __shared__ float warpred[BLK / 32];   // 20 entries
    if ((tid & 31) == 0) warpred[tid >> 5] = acc;
    __syncthreads();

    if (tid < 32) {
        float v = (tid < BLK / 32) ? warpred[tid] : 0.f;
#pragma unroll
        for (int off = 16; off > 0; off >>= 1)
            v += __shfl_down_sync(0xFFFFFFFFu, v, off);
        if (tid == 0) {
            const float d  = v + (bias[1] - bias[0]);   // l1 - l0
            const float ad = fabsf(d);
            const float t  = __logf(1.f + __expf(-ad)); // log1p(e^-|d|)
            const float lo = -(ad + t);                 // smaller logit
            const float hi = -t;                        // larger logit
            float2 o;
            o.x = (d >= 0.f) ? lo : hi;
            o.y = (d >= 0.f) ? hi : lo;
            *reinterpret_cast<float2*>(out + b * 2) = o;
        }
    }
}

extern "C" void kernel_launch(void* const* d_in, const int* in_sizes, int n_in,
                              void* d_out, int out_size)
{
    (void)in_sizes; (void)n_in; (void)out_size;
    const float* x    = (const float*)d_in[0];  // [64,100,100]
    const float* W    = (const float*)d_in[1];  // [2,10000]
    const float* bias = (const float*)d_in[2];  // [2]
    const float* qp   = (const float*)d_in[3];  // [6]

    fused_kernel<<<64, BLK>>>(x, W, bias, qp, (float*)d_out);
}